// round 1
// baseline (speedup 1.0000x reference)
#include <cuda_runtime.h>
#include <cstddef>

// Problem constants (fixed by setup_inputs)
#define B 512
#define L 100
#define M_NEG 10
#define D 256
#define NASP 14

// Output layout: r_s [B,D], z_s [B,D], z_n [B,M,D] flattened in tuple order
#define R_OFF   0
#define Z_OFF   (B * D)                 // 131072
#define ZN_OFF  (2 * B * D)             // 262144

// ---------------------------------------------------------------------------
// Block reduce (sum), 256 threads = 8 warps. Safe for repeated calls.
// ---------------------------------------------------------------------------
__device__ __forceinline__ float block_reduce_sum_256(float v, float* red) {
    #pragma unroll
    for (int o = 16; o > 0; o >>= 1) v += __shfl_down_sync(0xffffffffu, v, o);
    const int w = threadIdx.x >> 5, lane = threadIdx.x & 31;
    if (lane == 0) red[w] = v;
    __syncthreads();
    if (w == 0) {
        v = (lane < 8) ? red[lane] : 0.f;
        #pragma unroll
        for (int o = 4; o > 0; o >>= 1) v += __shfl_down_sync(0xffffffffu, v, o);
        if (lane == 0) red[0] = v;
    }
    __syncthreads();
    float r = red[0];
    __syncthreads();   // protect red[] before next use
    return r;
}

// ---------------------------------------------------------------------------
// Kernel 1: pos path. One CTA per batch element. 256 threads.
// Dynamic smem layout (floats):
//   e   [L*D]   = 25600
//   yv  [D]     = 256    (y_s, later reused for z_s)
//   My  [D]     = 256
//   wts [128]   (exp(tanh(d_i)) weights; also reused for logits)
//   red [32]
//   sidx[128]   (int)
// total = 26400 floats = 105600 bytes
// ---------------------------------------------------------------------------
extern "C" __global__ void __launch_bounds__(256)
abae_pos_kernel(const int* __restrict__ pos,
                const float* __restrict__ E_w,
                const float* __restrict__ T_w,
                const float* __restrict__ M_w,
                const float* __restrict__ M_b,
                const float* __restrict__ lin_w,
                const float* __restrict__ lin_b,
                float* __restrict__ out)
{
    extern __shared__ float smem[];
    float* e    = smem;                 // [L][D]
    float* yv   = e + L * D;            // [D]
    float* My   = yv + D;               // [D]
    float* wts  = My + D;               // [128]
    float* red  = wts + 128;            // [32]
    int*   sidx = (int*)(red + 32);     // [128]

    const int b   = blockIdx.x;
    const int tid = threadIdx.x;
    const int wid = tid >> 5, lane = tid & 31;

    if (tid < L) sidx[tid] = pos[b * L + tid];
    __syncthreads();

    // Gather e rows into smem; fuse y_s column sums (thread tid owns dim tid)
    float ysum = 0.f;
    #pragma unroll 4
    for (int l = 0; l < L; l++) {
        float val = E_w[((size_t)sidx[l] << 8) + tid];
        e[l * D + tid] = val;
        ysum += val;
    }
    yv[tid] = ysum * (1.0f / (float)L);
    __syncthreads();

    // My = M_w @ y_s + M_b  -- warp-cooperative per output row (coalesced M_w)
    for (int j = wid; j < D; j += 8) {
        float s = 0.f;
        const float* mrow = M_w + (size_t)j * D;
        #pragma unroll
        for (int k = lane; k < D; k += 32) s += mrow[k] * yv[k];
        #pragma unroll
        for (int o = 16; o > 0; o >>= 1) s += __shfl_down_sync(0xffffffffu, s, o);
        if (lane == 0) My[j] = s + M_b[j];
    }
    __syncthreads();

    // w[l] = exp(tanh(dot(e[l], My)))  -- global softmax denominator cancels in l2norm
    for (int l = wid; l < L; l += 8) {
        float s = 0.f;
        const float* erow = e + l * D;
        #pragma unroll
        for (int k = lane; k < D; k += 32) s += erow[k] * My[k];
        #pragma unroll
        for (int o = 16; o > 0; o >>= 1) s += __shfl_down_sync(0xffffffffu, s, o);
        if (lane == 0) wts[l] = __expf(tanhf(s));
    }
    __syncthreads();

    // v = sum_l w[l] * e[l]; z_s = v / max(||v||, eps)
    float v = 0.f;
    #pragma unroll 4
    for (int l = 0; l < L; l++) v += wts[l] * e[l * D + tid];

    float ss = block_reduce_sum_256(v * v, red);
    float z  = v / fmaxf(sqrtf(ss), 1e-12f);
    out[Z_OFF + (size_t)b * D + tid] = z;

    __syncthreads();        // yv reuse: all done reading yv above
    yv[tid] = z;            // stash z_s for logits
    __syncthreads();

    // logits[a] = dot(z, lin_w[a]) + lin_b[a]   (14 aspects)
    if (tid < NASP) {
        float lg = lin_b[tid];
        const float* lr = lin_w + (size_t)tid * D;
        #pragma unroll 8
        for (int k = 0; k < D; k++) lg += lr[k] * yv[k];
        wts[tid] = lg;
    }
    __syncthreads();

    // softmax (redundant per-thread, 14 elems) folded into T_w combine; l2norm after
    float mx = -1e30f;
    #pragma unroll
    for (int a = 0; a < NASP; a++) mx = fmaxf(mx, wts[a]);
    float psum = 0.f, r = 0.f;
    #pragma unroll
    for (int a = 0; a < NASP; a++) {
        float p = __expf(wts[a] - mx);
        psum += p;
        r += p * T_w[a * D + tid];
    }
    r /= psum;

    float rss = block_reduce_sum_256(r * r, red);
    out[R_OFF + (size_t)b * D + tid] = r / fmaxf(sqrtf(rss), 1e-12f);
}

// ---------------------------------------------------------------------------
// Kernel 2: negs path. One CTA per (b, m). 256 threads, thread owns one dim.
// z_n = l2norm(mean_L E_w[negs[b,m,:]])
// ---------------------------------------------------------------------------
extern "C" __global__ void __launch_bounds__(256)
abae_neg_kernel(const int* __restrict__ negs,
                const float* __restrict__ E_w,
                float* __restrict__ out)
{
    __shared__ int sidx[128];
    __shared__ float red[32];

    const int bm  = blockIdx.x;        // 0 .. B*M-1
    const int tid = threadIdx.x;

    if (tid < L) sidx[tid] = negs[(size_t)bm * L + tid];
    __syncthreads();

    float a0 = 0.f, a1 = 0.f, a2 = 0.f, a3 = 0.f;
    #pragma unroll
    for (int l = 0; l < L; l += 4) {
        a0 += E_w[((size_t)sidx[l + 0] << 8) + tid];
        a1 += E_w[((size_t)sidx[l + 1] << 8) + tid];
        a2 += E_w[((size_t)sidx[l + 2] << 8) + tid];
        a3 += E_w[((size_t)sidx[l + 3] << 8) + tid];
    }
    float acc = (a0 + a1) + (a2 + a3);

    float ss = block_reduce_sum_256(acc * acc, red);
    // mean = acc/L; norm(mean) = sqrt(ss)/L; z = mean / max(norm(mean), eps)
    float nm  = sqrtf(ss) * (1.0f / (float)L);
    float inv = (1.0f / (float)L) / fmaxf(nm, 1e-12f);
    out[ZN_OFF + (size_t)bm * D + tid] = acc * inv;
}

// ---------------------------------------------------------------------------
// Launch
// Inputs (metadata order): pos, negs, E_w, T_w, M_w, M_b, lin_w, lin_b
// ---------------------------------------------------------------------------
extern "C" void kernel_launch(void* const* d_in, const int* in_sizes, int n_in,
                              void* d_out, int out_size)
{
    const int*   pos   = (const int*)  d_in[0];
    const int*   negs  = (const int*)  d_in[1];
    const float* E_w   = (const float*)d_in[2];
    const float* T_w   = (const float*)d_in[3];
    const float* M_w   = (const float*)d_in[4];
    const float* M_b   = (const float*)d_in[5];
    const float* lin_w = (const float*)d_in[6];
    const float* lin_b = (const float*)d_in[7];
    float* out = (float*)d_out;

    const int smem_bytes = 26400 * 4;   // 105600 B dynamic smem for pos kernel
    cudaFuncSetAttribute(abae_pos_kernel,
                         cudaFuncAttributeMaxDynamicSharedMemorySize, smem_bytes);

    abae_pos_kernel<<<B, 256, smem_bytes>>>(pos, E_w, T_w, M_w, M_b, lin_w, lin_b, out);
    abae_neg_kernel<<<B * M_NEG, 256>>>(negs, E_w, out);
}

// round 2
// speedup vs baseline: 3.5345x; 3.5345x over previous
#include <cuda_runtime.h>
#include <cstddef>

// Problem constants (fixed by setup_inputs)
#define B 512
#define L 100
#define M_NEG 10
#define D 256
#define NASP 14

// Output layout: r_s [B,D], z_s [B,D], z_n [B,M,D]
#define R_OFF   0
#define Z_OFF   (B * D)
#define ZN_OFF  (2 * B * D)

struct __align__(16) Smem {
    float4 part[4][D / 4];   // group-partial sums (4 KB)
    float4 yv4[D / 4];       // y_s, later reused for z_s (1 KB)
    float4 My4[D / 4];       // M_w @ y_s + b (1 KB)
    float  wts[128];         // exp(tanh(d_i)) weights / logits
    float  red[32];
    int    sidx[128];
};

__device__ __forceinline__ float block_reduce_sum_256(float v, float* red) {
    #pragma unroll
    for (int o = 16; o > 0; o >>= 1) v += __shfl_down_sync(0xffffffffu, v, o);
    const int w = threadIdx.x >> 5, lane = threadIdx.x & 31;
    if (lane == 0) red[w] = v;
    __syncthreads();
    if (w == 0) {
        v = (lane < 8) ? red[lane] : 0.f;
        #pragma unroll
        for (int o = 4; o > 0; o >>= 1) v += __shfl_down_sync(0xffffffffu, v, o);
        if (lane == 0) red[0] = v;
    }
    __syncthreads();
    float r = red[0];
    __syncthreads();
    return r;
}

// Group-cooperative weighted row-sum gather:
//   thread (g = tid>>6, q = tid&63) accumulates float4 of dims [4q,4q+4)
//   over rows l = g, g+4, ...  Result combined across groups via smem.
// Returns this thread's final scalar for dim `tid`.
__device__ __forceinline__ float group_gather_sum(
    const float* __restrict__ E_w, Smem& sm, const float* wts /*nullable*/)
{
    const int tid = threadIdx.x;
    const int g = tid >> 6, q = tid & 63;
    float4 acc = make_float4(0.f, 0.f, 0.f, 0.f);
    #pragma unroll 5
    for (int l = g; l < L; l += 4) {
        const float4* row = reinterpret_cast<const float4*>(E_w) +
                            ((size_t)sm.sidx[l] << 6);
        float4 v = row[q];
        float w = wts ? wts[l] : 1.0f;
        acc.x = fmaf(w, v.x, acc.x);
        acc.y = fmaf(w, v.y, acc.y);
        acc.z = fmaf(w, v.z, acc.z);
        acc.w = fmaf(w, v.w, acc.w);
    }
    sm.part[g][q] = acc;
    __syncthreads();
    const float* p = reinterpret_cast<const float*>(sm.part);
    float s = p[0 * D + tid] + p[1 * D + tid] + p[2 * D + tid] + p[3 * D + tid];
    __syncthreads();   // part[] reusable afterwards
    return s;
}

__device__ __forceinline__ float dot8_shfl(float4 a0, float4 b0, float4 a1, float4 b1) {
    float s = a0.x * b0.x + a0.y * b0.y + a0.z * b0.z + a0.w * b0.w
            + a1.x * b1.x + a1.y * b1.y + a1.z * b1.z + a1.w * b1.w;
    #pragma unroll
    for (int o = 16; o > 0; o >>= 1) s += __shfl_down_sync(0xffffffffu, s, o);
    return s;
}

// ---------------------------------------------------------------------------
// Fat kernel: blocks [0, B) = pos path, blocks [B, B + B*M) = neg path.
// Pos blocks first so their latency chains hide under the neg bandwidth stream.
// ---------------------------------------------------------------------------
extern "C" __global__ void __launch_bounds__(256)
abae_fat_kernel(const int* __restrict__ pos,
                const int* __restrict__ negs,
                const float* __restrict__ E_w,
                const float* __restrict__ T_w,
                const float* __restrict__ M_w,
                const float* __restrict__ M_b,
                const float* __restrict__ lin_w,
                const float* __restrict__ lin_b,
                float* __restrict__ out)
{
    __shared__ Smem sm;
    const int tid = threadIdx.x;
    const int wid = tid >> 5, lane = tid & 31;

    if (blockIdx.x >= B) {
        // ---------------- NEG PATH:  z_n = l2norm(mean_L E_w[negs]) --------
        const int bm = blockIdx.x - B;
        if (tid < L) sm.sidx[tid] = negs[(size_t)bm * L + tid];
        __syncthreads();

        float s = group_gather_sum(E_w, sm, nullptr);
        float ss = block_reduce_sum_256(s * s, sm.red);
        // mean = s/L; z = mean / max(||mean||, eps); ||mean|| = sqrt(ss)/L
        float nm  = sqrtf(ss) * (1.0f / (float)L);
        float inv = (1.0f / (float)L) / fmaxf(nm, 1e-12f);
        out[ZN_OFF + (size_t)bm * D + tid] = s * inv;
        return;
    }

    // ------------------------- POS PATH --------------------------------
    const int b = blockIdx.x;
    float* yv  = reinterpret_cast<float*>(sm.yv4);
    float* Myf = reinterpret_cast<float*>(sm.My4);

    if (tid < L) sm.sidx[tid] = pos[(size_t)b * L + tid];
    __syncthreads();

    // Phase 1: y_s = mean_L e
    float ysum = group_gather_sum(E_w, sm, nullptr);
    yv[tid] = ysum * (1.0f / (float)L);
    __syncthreads();

    // Phase 2: My = M_w @ y_s + M_b   (warp-cooperative, float4 rows)
    for (int j = wid; j < D; j += 8) {
        const float4* mrow = reinterpret_cast<const float4*>(M_w + (size_t)j * D);
        float s = dot8_shfl(mrow[lane], sm.yv4[lane],
                            mrow[lane + 32], sm.yv4[lane + 32]);
        if (lane == 0) Myf[j] = s + M_b[j];
    }
    __syncthreads();

    // Phase 3: w[l] = exp(tanh(dot(e_l, My)))  (global softmax denom cancels in l2norm)
    for (int l = wid; l < L; l += 8) {
        const float4* erow = reinterpret_cast<const float4*>(E_w) +
                             ((size_t)sm.sidx[l] << 6);
        float s = dot8_shfl(erow[lane], sm.My4[lane],
                            erow[lane + 32], sm.My4[lane + 32]);
        if (lane == 0) sm.wts[l] = __expf(tanhf(s));
    }
    __syncthreads();

    // Phase 4: v = sum_l w[l] e_l ; z_s = v / max(||v||, eps)
    float v = group_gather_sum(E_w, sm, sm.wts);
    float ss = block_reduce_sum_256(v * v, sm.red);
    float z  = v / fmaxf(sqrtf(ss), 1e-12f);
    out[Z_OFF + (size_t)b * D + tid] = z;

    yv[tid] = z;                 // stash z_s (yv no longer read)
    __syncthreads();

    // Phase 5: logits[a] = dot(z, lin_w[a]) + lin_b[a]  (warp-per-aspect)
    for (int a = wid; a < NASP; a += 8) {
        const float4* lr = reinterpret_cast<const float4*>(lin_w + (size_t)a * D);
        float s = dot8_shfl(lr[lane], sm.yv4[lane],
                            lr[lane + 32], sm.yv4[lane + 32]);
        if (lane == 0) sm.wts[a] = s + lin_b[a];
    }
    __syncthreads();

    // Phase 6: softmax over 14 aspects folded into T_w combine, then l2norm
    float mx = -1e30f;
    #pragma unroll
    for (int a = 0; a < NASP; a++) mx = fmaxf(mx, sm.wts[a]);
    float psum = 0.f, r = 0.f;
    #pragma unroll
    for (int a = 0; a < NASP; a++) {
        float p = __expf(sm.wts[a] - mx);
        psum += p;
        r = fmaf(p, T_w[a * D + tid], r);
    }
    r /= psum;

    float rss = block_reduce_sum_256(r * r, sm.red);
    out[R_OFF + (size_t)b * D + tid] = r / fmaxf(sqrtf(rss), 1e-12f);
}

// ---------------------------------------------------------------------------
// Inputs (metadata order): pos, negs, E_w, T_w, M_w, M_b, lin_w, lin_b
// ---------------------------------------------------------------------------
extern "C" void kernel_launch(void* const* d_in, const int* in_sizes, int n_in,
                              void* d_out, int out_size)
{
    const int*   pos   = (const int*)  d_in[0];
    const int*   negs  = (const int*)  d_in[1];
    const float* E_w   = (const float*)d_in[2];
    const float* T_w   = (const float*)d_in[3];
    const float* M_w   = (const float*)d_in[4];
    const float* M_b   = (const float*)d_in[5];
    const float* lin_w = (const float*)d_in[6];
    const float* lin_b = (const float*)d_in[7];
    float* out = (float*)d_out;

    abae_fat_kernel<<<B + B * M_NEG, 256>>>(pos, negs, E_w, T_w, M_w, M_b,
                                            lin_w, lin_b, out);
}

// round 3
// speedup vs baseline: 4.0705x; 1.1517x over previous
#include <cuda_runtime.h>
#include <cstddef>

// Problem constants (fixed by setup_inputs)
#define B 512
#define L 100
#define M_NEG 10
#define D 256
#define NASP 14

// Output layout: r_s [B,D], z_s [B,D], z_n [B,M,D]
#define R_OFF   0
#define Z_OFF   (B * D)
#define ZN_OFF  (2 * B * D)

struct __align__(16) Smem {
    float4 part[4][D / 4];   // group-partial sums (4 KB)
    float4 yv4[D / 4];       // y_s, later reused for z_s (1 KB)
    float4 My4[D / 4];       // M_w @ y_s + b (1 KB)
    float  wts[128];         // exp(tanh(d_i)) weights / logits
    float  red[32];
    int    sidx[128];
};

__device__ __forceinline__ float block_reduce_sum_256(float v, float* red) {
    #pragma unroll
    for (int o = 16; o > 0; o >>= 1) v += __shfl_down_sync(0xffffffffu, v, o);
    const int w = threadIdx.x >> 5, lane = threadIdx.x & 31;
    if (lane == 0) red[w] = v;
    __syncthreads();
    if (w == 0) {
        v = (lane < 8) ? red[lane] : 0.f;
        #pragma unroll
        for (int o = 4; o > 0; o >>= 1) v += __shfl_down_sync(0xffffffffu, v, o);
        if (lane == 0) red[0] = v;
    }
    __syncthreads();
    float r = red[0];
    __syncthreads();
    return r;
}

__device__ __forceinline__ void fma4(float4& a, float w, const float4& v) {
    a.x = fmaf(w, v.x, a.x);
    a.y = fmaf(w, v.y, a.y);
    a.z = fmaf(w, v.z, a.z);
    a.w = fmaf(w, v.w, a.w);
}

// Group-cooperative weighted row-sum gather with TWO independent load/FMA
// chains for MLP. thread (g = tid>>6, q = tid&63) owns float4 of dims
// [4q,4q+4) over rows l = g, g+4, ... (25 rows per group).
__device__ __forceinline__ float group_gather_sum(
    const float* __restrict__ E_w, Smem& sm, const float* wts /*nullable*/)
{
    const int tid = threadIdx.x;
    const int g = tid >> 6, q = tid & 63;
    const float4* __restrict__ Ev = reinterpret_cast<const float4*>(E_w);

    float4 acc0 = make_float4(0.f, 0.f, 0.f, 0.f);
    float4 acc1 = make_float4(0.f, 0.f, 0.f, 0.f);

    int l = g;
    #pragma unroll
    for (int k = 0; k < 12; k++) {          // 12 pairs = rows g..g+92
        float4 v0 = Ev[((size_t)sm.sidx[l]     << 6) + q];
        float4 v1 = Ev[((size_t)sm.sidx[l + 4] << 6) + q];
        float w0 = wts ? wts[l]     : 1.0f;
        float w1 = wts ? wts[l + 4] : 1.0f;
        fma4(acc0, w0, v0);
        fma4(acc1, w1, v1);
        l += 8;
    }
    {                                        // remainder row g+96
        float4 v0 = Ev[((size_t)sm.sidx[l] << 6) + q];
        float w0 = wts ? wts[l] : 1.0f;
        fma4(acc0, w0, v0);
    }
    acc0.x += acc1.x; acc0.y += acc1.y; acc0.z += acc1.z; acc0.w += acc1.w;

    sm.part[g][q] = acc0;
    __syncthreads();
    const float* p = reinterpret_cast<const float*>(sm.part);
    float s = p[0 * D + tid] + p[1 * D + tid] + p[2 * D + tid] + p[3 * D + tid];
    __syncthreads();   // part[] reusable afterwards
    return s;
}

__device__ __forceinline__ float dot8_shfl(float4 a0, float4 b0, float4 a1, float4 b1) {
    float s = a0.x * b0.x + a0.y * b0.y + a0.z * b0.z + a0.w * b0.w
            + a1.x * b1.x + a1.y * b1.y + a1.z * b1.z + a1.w * b1.w;
    #pragma unroll
    for (int o = 16; o > 0; o >>= 1) s += __shfl_down_sync(0xffffffffu, s, o);
    return s;
}

// ---------------------------------------------------------------------------
// Fat kernel: blocks [0, B) = pos path, blocks [B, B + B*M) = neg path.
// __launch_bounds__(256, 8) forces 32 regs/thread -> 64 warps/SM.
// ---------------------------------------------------------------------------
extern "C" __global__ void __launch_bounds__(256, 8)
abae_fat_kernel(const int* __restrict__ pos,
                const int* __restrict__ negs,
                const float* __restrict__ E_w,
                const float* __restrict__ T_w,
                const float* __restrict__ M_w,
                const float* __restrict__ M_b,
                const float* __restrict__ lin_w,
                const float* __restrict__ lin_b,
                float* __restrict__ out)
{
    __shared__ Smem sm;
    const int tid = threadIdx.x;
    const int wid = tid >> 5, lane = tid & 31;

    if (blockIdx.x >= B) {
        // ---------------- NEG PATH:  z_n = l2norm(mean_L E_w[negs]) --------
        const int bm = blockIdx.x - B;
        if (tid < L) sm.sidx[tid] = negs[(size_t)bm * L + tid];
        __syncthreads();

        float s = group_gather_sum(E_w, sm, nullptr);
        float ss = block_reduce_sum_256(s * s, sm.red);
        float nm  = sqrtf(ss) * (1.0f / (float)L);
        float inv = (1.0f / (float)L) / fmaxf(nm, 1e-12f);
        out[ZN_OFF + (size_t)bm * D + tid] = s * inv;
        return;
    }

    // ------------------------- POS PATH --------------------------------
    const int b = blockIdx.x;
    float* yv  = reinterpret_cast<float*>(sm.yv4);
    float* Myf = reinterpret_cast<float*>(sm.My4);

    if (tid < L) sm.sidx[tid] = pos[(size_t)b * L + tid];
    __syncthreads();

    // Phase 1: y_s = mean_L e
    float ysum = group_gather_sum(E_w, sm, nullptr);
    yv[tid] = ysum * (1.0f / (float)L);
    __syncthreads();

    // Phase 2: My = M_w @ y_s + M_b   (warp-cooperative, float4 rows)
    for (int j = wid; j < D; j += 8) {
        const float4* mrow = reinterpret_cast<const float4*>(M_w + (size_t)j * D);
        float s = dot8_shfl(mrow[lane], sm.yv4[lane],
                            mrow[lane + 32], sm.yv4[lane + 32]);
        if (lane == 0) Myf[j] = s + M_b[j];
    }
    __syncthreads();

    // Phase 3: w[l] = exp(tanh(dot(e_l, My)))  (global softmax denom cancels in l2norm)
    for (int l = wid; l < L; l += 8) {
        const float4* erow = reinterpret_cast<const float4*>(E_w) +
                             ((size_t)sm.sidx[l] << 6);
        float s = dot8_shfl(erow[lane], sm.My4[lane],
                            erow[lane + 32], sm.My4[lane + 32]);
        if (lane == 0) sm.wts[l] = __expf(tanhf(s));
    }
    __syncthreads();

    // Phase 4: v = sum_l w[l] e_l ; z_s = v / max(||v||, eps)
    float v = group_gather_sum(E_w, sm, sm.wts);
    float ss = block_reduce_sum_256(v * v, sm.red);
    float z  = v / fmaxf(sqrtf(ss), 1e-12f);
    out[Z_OFF + (size_t)b * D + tid] = z;

    yv[tid] = z;                 // stash z_s (yv no longer read)
    __syncthreads();

    // Phase 5: logits[a] = dot(z, lin_w[a]) + lin_b[a]  (warp-per-aspect)
    for (int a = wid; a < NASP; a += 8) {
        const float4* lr = reinterpret_cast<const float4*>(lin_w + (size_t)a * D);
        float s = dot8_shfl(lr[lane], sm.yv4[lane],
                            lr[lane + 32], sm.yv4[lane + 32]);
        if (lane == 0) sm.wts[a] = s + lin_b[a];
    }
    __syncthreads();

    // Phase 6: softmax over 14 aspects folded into T_w combine, then l2norm
    float mx = -1e30f;
    #pragma unroll
    for (int a = 0; a < NASP; a++) mx = fmaxf(mx, sm.wts[a]);
    float psum = 0.f, r = 0.f;
    #pragma unroll
    for (int a = 0; a < NASP; a++) {
        float p = __expf(sm.wts[a] - mx);
        psum += p;
        r = fmaf(p, T_w[a * D + tid], r);
    }
    r /= psum;

    float rss = block_reduce_sum_256(r * r, sm.red);
    out[R_OFF + (size_t)b * D + tid] = r / fmaxf(sqrtf(rss), 1e-12f);
}

// ---------------------------------------------------------------------------
// Inputs (metadata order): pos, negs, E_w, T_w, M_w, M_b, lin_w, lin_b
// ---------------------------------------------------------------------------
extern "C" void kernel_launch(void* const* d_in, const int* in_sizes, int n_in,
                              void* d_out, int out_size)
{
    const int*   pos   = (const int*)  d_in[0];
    const int*   negs  = (const int*)  d_in[1];
    const float* E_w   = (const float*)d_in[2];
    const float* T_w   = (const float*)d_in[3];
    const float* M_w   = (const float*)d_in[4];
    const float* M_b   = (const float*)d_in[5];
    const float* lin_w = (const float*)d_in[6];
    const float* lin_b = (const float*)d_in[7];
    float* out = (float*)d_out;

    abae_fat_kernel<<<B + B * M_NEG, 256>>>(pos, negs, E_w, T_w, M_w, M_b,
                                            lin_w, lin_b, out);
}